// round 7
// baseline (speedup 1.0000x reference)
#include <cuda_runtime.h>
#include <cuda_bf16.h>
#include <stdint.h>

#define NN 100000
#define NE 1250000
#define BKT 64
#define TILE_M 128
#define NTILES ((NN + TILE_M - 1) / TILE_M)   // 782

// ---- static device scratch (no allocations) ----
__device__ int g_cnt[NN];           // degree counter / scatter cursor
__device__ int g_src[NN * BKT];     // padded neighbor buckets (25.6 MB)

// ---- dynamic shared layout (byte offsets; rows are 256B, XOR-16B swizzled) ----
#define OFF_AH   0        // A hi tile: 128 rows x 128 bf16 (x||mean), 32 KB
#define OFF_AL   32768    // A lo tile, 32 KB
#define OFF_BH   65536    // B hi tile: 64 rows x 128 bf16 (W' = [Ws|Wn] per row), 16 KB
#define OFF_BL   81920    // B lo tile, 16 KB
#define OFF_BIAS 98304    // 64 floats
#define SMEM_USE 98560
#define SMEM_DYN (SMEM_USE + 256)

__device__ __forceinline__ uint32_t s2u(const void* p) {
    uint32_t a;
    asm("{ .reg .u64 t; cvta.to.shared.u64 t, %1; cvt.u32.u64 %0, t; }" : "=r"(a) : "l"(p));
    return a;
}

// split a float2 into packed bf16x2 hi + bf16x2 residual
__device__ __forceinline__ void bsplit(float2 v, uint32_t& h, uint32_t& l) {
    __nv_bfloat162 h2 = __floats2bfloat162_rn(v.x, v.y);
    float hx = __bfloat162float(__low2bfloat16(h2));
    float hy = __bfloat162float(__high2bfloat16(h2));
    __nv_bfloat162 l2 = __floats2bfloat162_rn(v.x - hx, v.y - hy);
    h = *(uint32_t*)&h2;
    l = *(uint32_t*)&l2;
}

__device__ __forceinline__ void ldsm4(uint32_t* r, uint32_t addr) {
    asm volatile("ldmatrix.sync.aligned.m8n8.x4.shared.b16 {%0,%1,%2,%3}, [%4];"
                 : "=r"(r[0]), "=r"(r[1]), "=r"(r[2]), "=r"(r[3]) : "r"(addr));
}
// B is [n][k] with k contiguous -> NON-transposed ldmatrix matches the
// mma.row.col B fragment (consecutive k within a register). (.trans was the r6 bug.)
__device__ __forceinline__ void ldsm2(uint32_t* r, uint32_t addr) {
    asm volatile("ldmatrix.sync.aligned.m8n8.x2.shared.b16 {%0,%1}, [%2];"
                 : "=r"(r[0]), "=r"(r[1]) : "r"(addr));
}
__device__ __forceinline__ void mma16816(float* c, const uint32_t* a, const uint32_t* b) {
    asm volatile(
        "mma.sync.aligned.m16n8k16.row.col.f32.bf16.bf16.f32 "
        "{%0,%1,%2,%3}, {%4,%5,%6,%7}, {%8,%9}, {%0,%1,%2,%3};"
        : "+f"(c[0]), "+f"(c[1]), "+f"(c[2]), "+f"(c[3])
        : "r"(a[0]), "r"(a[1]), "r"(a[2]), "r"(a[3]), "r"(b[0]), "r"(b[1]));
}

// ---------------------------------------------------------------------------
// Scatter edges into padded buckets.
// ---------------------------------------------------------------------------
__global__ void k_scatter(const int* __restrict__ ei, int E) {
    int e = blockIdx.x * blockDim.x + threadIdx.x;
    if (e < E) {
        int dst = __ldg(ei + E + e);
        int src = __ldg(ei + e);
        int pos = atomicAdd(&g_cnt[dst], 1);
        if (pos < BKT) g_src[dst * BKT + pos] = src;
    }
}

// ---------------------------------------------------------------------------
// Fused: gather neighbor-mean -> split-bf16 A tile -> mma.sync GEMM -> epilogue.
// Block = 256 thr = 8 warps, one 128-node tile. Warp w: rows [16w,16w+16).
// A row k-layout: [x feats 0-63 | mean feats 0-63]. B[n][k] = W'[n][k].
// C = Ah*Bh + Ah*Bl + Al*Bh  (fp32 accum; dropped Al*Bl ~ 2^-16 rel).
// ---------------------------------------------------------------------------
__global__ void __launch_bounds__(256, 2)
k_fused(const float* __restrict__ x,
        const float* __restrict__ Ws,
        const float* __restrict__ bs,
        const float* __restrict__ Wn,
        float* __restrict__ out) {
    extern __shared__ char smem_raw[];
    uint32_t sb32 = (s2u(smem_raw) + 255u) & ~255u;
    char* smem = smem_raw + (sb32 - s2u(smem_raw));
    int tid = threadIdx.x, lane = tid & 31, wid = tid >> 5;

    // ---- stage B (weights, split) + bias ----
    for (int idx = tid; idx < 64 * 64; idx += 256) {
        int n = idx >> 6, k2 = idx & 63;
        int k0 = 2 * k2, k1 = 2 * k2 + 1;
        float w0 = (k0 < 64) ? __ldg(Ws + n * 64 + k0) : __ldg(Wn + n * 64 + (k0 - 64));
        float w1 = (k1 < 64) ? __ldg(Ws + n * 64 + k1) : __ldg(Wn + n * 64 + (k1 - 64));
        uint32_t h, l;
        bsplit(make_float2(w0, w1), h, l);
        uint32_t c = (uint32_t)(4 * k2) ^ (uint32_t)((n & 7) << 4);   // swizzled byte in row
        *(uint32_t*)(smem + OFF_BH + n * 256 + c) = h;
        *(uint32_t*)(smem + OFF_BL + n * 256 + c) = l;
    }
    if (tid < 64) *(float*)(smem + OFF_BIAS + tid * 4) = __ldg(bs + tid);

    // ---- gather + stage A (warp w: rows 16w..16w+15; lane: feature pair 2l,2l+1) ----
    int base = blockIdx.x * TILE_M;
    const float2* xp = (const float2*)x;
    for (int i = 0; i < 16; i++) {
        int r = wid * 16 + i;
        int n = base + r;
        float2 xpair = make_float2(0.f, 0.f), mpair = make_float2(0.f, 0.f);
        if (n < NN) {
            int degRaw = __ldg(&g_cnt[n]);
            int deg = min(degRaw, BKT);
            const int* bkt = g_src + n * BKT;
            float ax = 0.f, ay = 0.f;
            int e = 0;
            for (; e + 8 <= deg; e += 8) {               // MLP = 8
                int4 s0 = *(const int4*)(bkt + e);
                int4 s1 = *(const int4*)(bkt + e + 4);
                float2 v0 = __ldg(xp + s0.x * 32 + lane);
                float2 v1 = __ldg(xp + s0.y * 32 + lane);
                float2 v2 = __ldg(xp + s0.z * 32 + lane);
                float2 v3 = __ldg(xp + s0.w * 32 + lane);
                float2 v4 = __ldg(xp + s1.x * 32 + lane);
                float2 v5 = __ldg(xp + s1.y * 32 + lane);
                float2 v6 = __ldg(xp + s1.z * 32 + lane);
                float2 v7 = __ldg(xp + s1.w * 32 + lane);
                ax += ((v0.x + v1.x) + (v2.x + v3.x)) + ((v4.x + v5.x) + (v6.x + v7.x));
                ay += ((v0.y + v1.y) + (v2.y + v3.y)) + ((v4.y + v5.y) + (v6.y + v7.y));
            }
            for (; e + 4 <= deg; e += 4) {
                int4 s = *(const int4*)(bkt + e);
                float2 v0 = __ldg(xp + s.x * 32 + lane);
                float2 v1 = __ldg(xp + s.y * 32 + lane);
                float2 v2 = __ldg(xp + s.z * 32 + lane);
                float2 v3 = __ldg(xp + s.w * 32 + lane);
                ax += (v0.x + v1.x) + (v2.x + v3.x);
                ay += (v0.y + v1.y) + (v2.y + v3.y);
            }
            for (; e < deg; e++) {
                int s = __ldg(bkt + e);
                float2 v = __ldg(xp + s * 32 + lane);
                ax += v.x; ay += v.y;
            }
            float inv = 1.f / fmaxf((float)degRaw, 1.f);
            xpair = __ldg(xp + n * 32 + lane);
            mpair = make_float2(ax * inv, ay * inv);
        }
        uint32_t sw = (uint32_t)((r & 7) << 4);
        uint32_t hx, lx, hm, lm;
        bsplit(xpair, hx, lx);
        bsplit(mpair, hm, lm);
        uint32_t cx = (uint32_t)(4 * lane) ^ sw;          // x part: bytes 0..127
        uint32_t cm = (uint32_t)(128 + 4 * lane) ^ sw;    // mean part: bytes 128..255
        *(uint32_t*)(smem + OFF_AH + r * 256 + cx) = hx;
        *(uint32_t*)(smem + OFF_AL + r * 256 + cx) = lx;
        *(uint32_t*)(smem + OFF_AH + r * 256 + cm) = hm;
        *(uint32_t*)(smem + OFF_AL + r * 256 + cm) = lm;
    }
    __syncthreads();

    // ---- GEMM: warp w computes rows [16w,16w+16) x all 64 cols ----
    int rm = wid * 16;
    int arow = rm + (lane & 7) + ((lane >> 3) & 1) * 8;   // ldmatrix x4 row per lane
    uint32_t koffA = (uint32_t)((lane >> 4) * 16);
    uint32_t swA = (uint32_t)((arow & 7) << 4);
    uint32_t aBase = sb32 + OFF_AH + (uint32_t)arow * 256;

    int Lb = lane & 15;                                    // ldmatrix x2 lanes
    uint32_t koffB = (uint32_t)((Lb >> 3) * 16);
    uint32_t swB = (uint32_t)((Lb & 7) << 4);
    uint32_t bBase = sb32 + OFF_BH + (uint32_t)(Lb & 7) * 256;

    float c[8][4];
    #pragma unroll
    for (int nt = 0; nt < 8; nt++)
        c[nt][0] = c[nt][1] = c[nt][2] = c[nt][3] = 0.f;

    #pragma unroll
    for (int ks = 0; ks < 8; ks++) {
        uint32_t ah[4], al[4];
        uint32_t aaddr = aBase + (((uint32_t)(ks * 32) + koffA) ^ swA);
        ldsm4(ah, aaddr);
        ldsm4(al, aaddr + 32768);
        uint32_t kb = ((uint32_t)(ks * 32) + koffB) ^ swB;
        #pragma unroll
        for (int nt = 0; nt < 8; nt++) {
            uint32_t bh[2], bl[2];
            uint32_t baddr = bBase + (uint32_t)(nt * 2048) + kb;
            ldsm2(bh, baddr);
            ldsm2(bl, baddr + 16384);
            mma16816(c[nt], ah, bh);
            mma16816(c[nt], ah, bl);
            mma16816(c[nt], al, bh);
        }
    }

    // ---- epilogue: bias + relu + store ----
    const float* bias = (const float*)(smem + OFF_BIAS);
    int r0 = base + rm + (lane >> 2);
    int colq = (lane & 3) * 2;
    #pragma unroll
    for (int nt = 0; nt < 8; nt++) {
        int col = nt * 8 + colq;
        float b0 = bias[col], b1 = bias[col + 1];
        if (r0 < NN) {
            float2 v;
            v.x = fmaxf(c[nt][0] + b0, 0.f);
            v.y = fmaxf(c[nt][1] + b1, 0.f);
            *(float2*)(out + (size_t)r0 * 64 + col) = v;
        }
        if (r0 + 8 < NN) {
            float2 v;
            v.x = fmaxf(c[nt][2] + b0, 0.f);
            v.y = fmaxf(c[nt][3] + b1, 0.f);
            *(float2*)(out + (size_t)(r0 + 8) * 64 + col) = v;
        }
    }
}

// ---------------------------------------------------------------------------
extern "C" void kernel_launch(void* const* d_in, const int* in_sizes, int n_in,
                              void* d_out, int out_size) {
    const float* x  = (const float*)d_in[0];
    const int*   ei = (const int*)  d_in[1];
    const float* Ws = (const float*)d_in[2];
    const float* bs = (const float*)d_in[3];
    const float* Wn = (const float*)d_in[4];
    float* out = (float*)d_out;
    int E = in_sizes[1] / 2;

    cudaFuncSetAttribute(k_fused, cudaFuncAttributeMaxDynamicSharedMemorySize, SMEM_DYN);

    void* cnt_ptr = nullptr;
    cudaGetSymbolAddress(&cnt_ptr, g_cnt);
    cudaMemsetAsync(cnt_ptr, 0, NN * sizeof(int));

    k_scatter<<<(E + 255) / 256, 256>>>(ei, E);
    k_fused<<<NTILES, 256, SMEM_DYN>>>(x, Ws, bs, Wn, out);
}

// round 8
// speedup vs baseline: 1.4015x; 1.4015x over previous
#include <cuda_runtime.h>
#include <cuda_bf16.h>
#include <stdint.h>

#define NN 100000
#define NE 1250000
#define BKT 64
#define TILE_M 128
#define NTILES ((NN + TILE_M - 1) / TILE_M)   // 782

// ---- static device scratch (no allocations) ----
__device__ int   g_cnt[NN];          // degree counter / scatter cursor
__device__ int   g_src[NN * BKT];    // padded neighbor buckets (25.6 MB)
__device__ float g_mean[NN * 64];    // neighbor means (25.6 MB)

// ---- k_gemm shared layout (byte offsets; rows 256B, XOR-16B swizzled) ----
#define OFF_AH   0        // A hi: 128 rows x 128 bf16 (x||mean), 32 KB
#define OFF_AL   32768    // A lo, 32 KB
#define OFF_BH   65536    // B hi: 64 rows x 128 bf16 (W'=[Ws|Wn]), 16 KB
#define OFF_BL   81920    // B lo, 16 KB
#define OFF_BIAS 98304    // 64 floats
#define SMEM_USE 98560
#define SMEM_DYN (SMEM_USE + 256)

__device__ __forceinline__ uint32_t s2u(const void* p) {
    uint32_t a;
    asm("{ .reg .u64 t; cvta.to.shared.u64 t, %1; cvt.u32.u64 %0, t; }" : "=r"(a) : "l"(p));
    return a;
}
__device__ __forceinline__ void bsplit(float2 v, uint32_t& h, uint32_t& l) {
    __nv_bfloat162 h2 = __floats2bfloat162_rn(v.x, v.y);
    float hx = __bfloat162float(__low2bfloat16(h2));
    float hy = __bfloat162float(__high2bfloat16(h2));
    __nv_bfloat162 l2 = __floats2bfloat162_rn(v.x - hx, v.y - hy);
    h = *(uint32_t*)&h2;
    l = *(uint32_t*)&l2;
}
__device__ __forceinline__ void ldsm4(uint32_t* r, uint32_t addr) {
    asm volatile("ldmatrix.sync.aligned.m8n8.x4.shared.b16 {%0,%1,%2,%3}, [%4];"
                 : "=r"(r[0]), "=r"(r[1]), "=r"(r[2]), "=r"(r[3]) : "r"(addr));
}
__device__ __forceinline__ void mma16816(float* c, const uint32_t* a, const uint32_t* b) {
    asm volatile(
        "mma.sync.aligned.m16n8k16.row.col.f32.bf16.bf16.f32 "
        "{%0,%1,%2,%3}, {%4,%5,%6,%7}, {%8,%9}, {%0,%1,%2,%3};"
        : "+f"(c[0]), "+f"(c[1]), "+f"(c[2]), "+f"(c[3])
        : "r"(a[0]), "r"(a[1]), "r"(a[2]), "r"(a[3]), "r"(b[0]), "r"(b[1]));
}

// ---------------------------------------------------------------------------
// Scatter edges into padded buckets.
// ---------------------------------------------------------------------------
__global__ void k_scatter(const int* __restrict__ ei, int E) {
    int e = blockIdx.x * blockDim.x + threadIdx.x;
    if (e < E) {
        int dst = __ldg(ei + E + e);
        int src = __ldg(ei + e);
        int pos = atomicAdd(&g_cnt[dst], 1);
        if (pos < BKT) g_src[dst * BKT + pos] = src;
    }
}

// ---------------------------------------------------------------------------
// Gather: warp per node, high occupancy (no smem, lean regs). Lane covers
// feature pair (2l, 2l+1). Writes neighbor mean to g_mean.
// ---------------------------------------------------------------------------
__global__ void __launch_bounds__(256)
k_gather(const float* __restrict__ x) {
    int gw = (blockIdx.x * 256 + threadIdx.x) >> 5;
    int lane = threadIdx.x & 31;
    if (gw >= NN) return;
    int n = gw;
    const float2* xp = (const float2*)x;

    int degRaw = __ldg(&g_cnt[n]);
    int deg = min(degRaw, BKT);
    const int* bkt = g_src + n * BKT;
    float ax = 0.f, ay = 0.f;
    int e = 0;
    for (; e + 8 <= deg; e += 8) {                  // MLP = 8
        int4 s0 = *(const int4*)(bkt + e);
        int4 s1 = *(const int4*)(bkt + e + 4);
        float2 v0 = __ldg(xp + s0.x * 32 + lane);
        float2 v1 = __ldg(xp + s0.y * 32 + lane);
        float2 v2 = __ldg(xp + s0.z * 32 + lane);
        float2 v3 = __ldg(xp + s0.w * 32 + lane);
        float2 v4 = __ldg(xp + s1.x * 32 + lane);
        float2 v5 = __ldg(xp + s1.y * 32 + lane);
        float2 v6 = __ldg(xp + s1.z * 32 + lane);
        float2 v7 = __ldg(xp + s1.w * 32 + lane);
        ax += ((v0.x + v1.x) + (v2.x + v3.x)) + ((v4.x + v5.x) + (v6.x + v7.x));
        ay += ((v0.y + v1.y) + (v2.y + v3.y)) + ((v4.y + v5.y) + (v6.y + v7.y));
    }
    for (; e + 4 <= deg; e += 4) {
        int4 s = *(const int4*)(bkt + e);
        float2 v0 = __ldg(xp + s.x * 32 + lane);
        float2 v1 = __ldg(xp + s.y * 32 + lane);
        float2 v2 = __ldg(xp + s.z * 32 + lane);
        float2 v3 = __ldg(xp + s.w * 32 + lane);
        ax += (v0.x + v1.x) + (v2.x + v3.x);
        ay += (v0.y + v1.y) + (v2.y + v3.y);
    }
    for (; e < deg; e++) {
        int s = __ldg(bkt + e);
        float2 v = __ldg(xp + s * 32 + lane);
        ax += v.x; ay += v.y;
    }
    float inv = 1.f / fmaxf((float)degRaw, 1.f);
    ((float2*)g_mean)[n * 32 + lane] = make_float2(ax * inv, ay * inv);
}

// ---------------------------------------------------------------------------
// GEMM: dense A staging (x + g_mean), split-bf16 HMMA, bias+ReLU epilogue.
// Block = 256 thr = 8 warps, one 128-node tile. Warp w: rows [16w,16w+16).
// C = Ah*Bh + Ah*Bl + Al*Bh.
// ---------------------------------------------------------------------------
__global__ void __launch_bounds__(256, 2)
k_gemm(const float* __restrict__ x,
       const float* __restrict__ Ws,
       const float* __restrict__ bs,
       const float* __restrict__ Wn,
       float* __restrict__ out) {
    extern __shared__ char smem_raw[];
    uint32_t sb32 = (s2u(smem_raw) + 255u) & ~255u;
    char* smem = smem_raw + (sb32 - s2u(smem_raw));
    int tid = threadIdx.x, lane = tid & 31, wid = tid >> 5;

    // ---- stage B (weights, split) + bias ----
    for (int idx = tid; idx < 64 * 64; idx += 256) {
        int n = idx >> 6, k2 = idx & 63;
        int k0 = 2 * k2, k1 = 2 * k2 + 1;
        float w0 = (k0 < 64) ? __ldg(Ws + n * 64 + k0) : __ldg(Wn + n * 64 + (k0 - 64));
        float w1 = (k1 < 64) ? __ldg(Ws + n * 64 + k1) : __ldg(Wn + n * 64 + (k1 - 64));
        uint32_t h, l;
        bsplit(make_float2(w0, w1), h, l);
        uint32_t c = (uint32_t)(4 * k2) ^ (uint32_t)((n & 7) << 4);
        *(uint32_t*)(smem + OFF_BH + n * 256 + c) = h;
        *(uint32_t*)(smem + OFF_BL + n * 256 + c) = l;
    }
    if (tid < 64) *(float*)(smem + OFF_BIAS + tid * 4) = __ldg(bs + tid);

    // ---- stage A: dense coalesced loads (x row + mean row), split-bf16 ----
    int base = blockIdx.x * TILE_M;
    const float2* xp = (const float2*)x;
    const float2* mp = (const float2*)g_mean;
    #pragma unroll 4
    for (int i = 0; i < 16; i++) {
        int r = wid * 16 + i;
        int n = base + r;
        float2 xpair = make_float2(0.f, 0.f), mpair = make_float2(0.f, 0.f);
        if (n < NN) {
            xpair = __ldg(xp + n * 32 + lane);
            mpair = __ldg(mp + n * 32 + lane);
        }
        uint32_t sw = (uint32_t)((r & 7) << 4);
        uint32_t hx, lx, hm, lm;
        bsplit(xpair, hx, lx);
        bsplit(mpair, hm, lm);
        uint32_t cx = (uint32_t)(4 * lane) ^ sw;
        uint32_t cm = (uint32_t)(128 + 4 * lane) ^ sw;
        *(uint32_t*)(smem + OFF_AH + r * 256 + cx) = hx;
        *(uint32_t*)(smem + OFF_AL + r * 256 + cx) = lx;
        *(uint32_t*)(smem + OFF_AH + r * 256 + cm) = hm;
        *(uint32_t*)(smem + OFF_AL + r * 256 + cm) = lm;
    }
    __syncthreads();

    // ---- GEMM: warp w -> rows [16w,16w+16) x 64 cols ----
    int rm = wid * 16;
    int arow = rm + (lane & 7) + ((lane >> 3) & 1) * 8;
    uint32_t koffA = (uint32_t)((lane >> 4) * 16);
    uint32_t swA = (uint32_t)((arow & 7) << 4);
    uint32_t aBase = sb32 + OFF_AH + (uint32_t)arow * 256;

    // B via ldmatrix.x4: lanes 0-7 n0-7/k+0, 8-15 n0-7/k+8, 16-23 n8-15/k+0, 24-31 n8-15/k+8
    int bn = (lane & 7) + ((lane >> 4) << 3);       // n-row within 16-row pair
    uint32_t koffB = (uint32_t)(((lane >> 3) & 1) * 16);
    uint32_t swB = (uint32_t)((bn & 7) << 4);
    uint32_t bBase = sb32 + OFF_BH + (uint32_t)bn * 256;

    float c[8][4];
    #pragma unroll
    for (int nt = 0; nt < 8; nt++)
        c[nt][0] = c[nt][1] = c[nt][2] = c[nt][3] = 0.f;

    #pragma unroll
    for (int ks = 0; ks < 8; ks++) {
        uint32_t ah[4], al[4];
        uint32_t aaddr = aBase + (((uint32_t)(ks * 32) + koffA) ^ swA);
        ldsm4(ah, aaddr);
        ldsm4(al, aaddr + 32768);
        uint32_t kbA = ((uint32_t)(ks * 32) + koffB) ^ swB;
        #pragma unroll
        for (int np = 0; np < 4; np++) {            // pair of n8-tiles per x4
            uint32_t bh[4], bl[4];
            uint32_t baddr = bBase + (uint32_t)(np * 4096) + kbA;
            ldsm4(bh, baddr);
            ldsm4(bl, baddr + 16384);
            mma16816(c[2 * np],     ah, bh);
            mma16816(c[2 * np],     ah, bl);
            mma16816(c[2 * np],     al, bh);
            mma16816(c[2 * np + 1], ah, bh + 2);
            mma16816(c[2 * np + 1], ah, bl + 2);
            mma16816(c[2 * np + 1], al, bh + 2);
        }
    }

    // ---- epilogue: bias + relu + store ----
    const float* bias = (const float*)(smem + OFF_BIAS);
    int r0 = base + rm + (lane >> 2);
    int colq = (lane & 3) * 2;
    #pragma unroll
    for (int nt = 0; nt < 8; nt++) {
        int col = nt * 8 + colq;
        float b0 = bias[col], b1 = bias[col + 1];
        if (r0 < NN) {
            float2 v;
            v.x = fmaxf(c[nt][0] + b0, 0.f);
            v.y = fmaxf(c[nt][1] + b1, 0.f);
            *(float2*)(out + (size_t)r0 * 64 + col) = v;
        }
        if (r0 + 8 < NN) {
            float2 v;
            v.x = fmaxf(c[nt][2] + b0, 0.f);
            v.y = fmaxf(c[nt][3] + b1, 0.f);
            *(float2*)(out + (size_t)(r0 + 8) * 64 + col) = v;
        }
    }
}

// ---------------------------------------------------------------------------
extern "C" void kernel_launch(void* const* d_in, const int* in_sizes, int n_in,
                              void* d_out, int out_size) {
    const float* x  = (const float*)d_in[0];
    const int*   ei = (const int*)  d_in[1];
    const float* Ws = (const float*)d_in[2];
    const float* bs = (const float*)d_in[3];
    const float* Wn = (const float*)d_in[4];
    float* out = (float*)d_out;
    int E = in_sizes[1] / 2;

    cudaFuncSetAttribute(k_gemm, cudaFuncAttributeMaxDynamicSharedMemorySize, SMEM_DYN);

    void* cnt_ptr = nullptr;
    cudaGetSymbolAddress(&cnt_ptr, g_cnt);
    cudaMemsetAsync(cnt_ptr, 0, NN * sizeof(int));

    k_scatter<<<(E + 255) / 256, 256>>>(ei, E);
    k_gather<<<(NN + 7) / 8, 256>>>(x);
    k_gemm<<<NTILES, 256, SMEM_DYN>>>(x, Ws, bs, Wn, out);
}